// round 15
// baseline (speedup 1.0000x reference)
#include <cuda_runtime.h>
#include <cuda_fp16.h>
#include <cstdint>
#include <cstddef>

// Shapes: batch[16,1024,1024] -> M=16384,K=1024 ; W1[1024,1024] ; W2[1024,128]
// out[16,1024,1024] fp32.
static const int M_TOT = 16384;
static const int D_DIM = 1024;
static const int H_DIM = 1024;
static const int R_DIM = 128;
static const int L_DIM = 1024;
static const int B_DIM = 16;

// ---- scratch (__device__ globals; no runtime allocation allowed) ----
__device__ __align__(256) __half g_a_hi[(size_t)16384 * 1024];
__device__ __align__(256) __half g_h_hi[(size_t)16384 * 1024];
__device__ __align__(256) __half g_w1t_hi[(size_t)1024 * 1024];
__device__ __align__(256) __half g_w2t_hi[(size_t)128 * 1024];
__device__ __align__(256) __half g_w2t_lo[(size_t)128 * 1024];
__device__ __align__(256) __half g_t_hi[(size_t)16384 * 128];
__device__ __align__(256) __half g_t_lo[(size_t)16384 * 128];
__device__ __align__(256) float g_sq[16384];

// ---------------- PTX helpers ----------------
__device__ __forceinline__ uint32_t smem_u32(const void* p) {
    uint32_t a;
    asm("{ .reg .u64 t; cvta.to.shared.u64 t, %1; cvt.u32.u64 %0, t; }" : "=r"(a) : "l"(p));
    return a;
}
__device__ __forceinline__ void cp16(uint32_t saddr, const void* g) {
    asm volatile("cp.async.cg.shared.global [%0], [%1], 16;" :: "r"(saddr), "l"(g));
}
__device__ __forceinline__ void cp_commit() {
    asm volatile("cp.async.commit_group;" ::: "memory");
}
__device__ __forceinline__ void ldsm4(uint32_t* r, uint32_t addr) {
    asm volatile("ldmatrix.sync.aligned.m8n8.x4.shared.b16 {%0,%1,%2,%3}, [%4];"
                 : "=r"(r[0]), "=r"(r[1]), "=r"(r[2]), "=r"(r[3]) : "r"(addr));
}
__device__ __forceinline__ void mma_f16(float* c, const uint32_t* a, const uint32_t* b) {
    asm volatile(
        "mma.sync.aligned.m16n8k16.row.col.f32.f16.f16.f32 "
        "{%0,%1,%2,%3}, {%4,%5,%6,%7}, {%8,%9}, {%0,%1,%2,%3};"
        : "+f"(c[0]), "+f"(c[1]), "+f"(c[2]), "+f"(c[3])
        : "r"(a[0]), "r"(a[1]), "r"(a[2]), "r"(a[3]), "r"(b[0]), "r"(b[1]));
}

// ---------------- unified tensor-core GEMM ------------------------
// acc = A @ B^T, fp16 operands, fp32 accumulate.
// MODE 0 (GEMM1): BM=128, BK=64,  3 stages, 1 product;  C=relu(acc+bias)->hi
// MODE 1 (GEMM2): BM=64,  BK=64,  2 stages, 2 products; C->hi/lo + sumsq->Cf
// MODE 2 (DIST):  BM=128, BK=128, SINGLE STAGE (whole K), 2 products;
//                 SYMMETRIC 36 triangle pairs; direct + mirrored block.
// 8 warps as 2(m) x 4(n); warp tile (BM/2) x 32.
template <int MODE>
__global__ __launch_bounds__(256, 2)
void mma_gemm(const __half* __restrict__ Ahi,
              const __half* __restrict__ Bhi, const __half* __restrict__ Blo,
              const float* __restrict__ bias,
              float* __restrict__ Cf,
              __half* __restrict__ Chi, __half* __restrict__ Clo,
              int K, int Ncols) {
    constexpr int NPROD = (MODE == 0) ? 1 : 2;
    constexpr int MI   = (MODE == 1) ? 2 : 4;      // 16-row frags per warp
    constexpr int BM   = MI * 32;
    constexpr int BK   = (MODE == 2) ? 128 : 64;
    constexpr int ROWB = BK * 2;                   // 128 / 128 / 256
    constexpr int KS   = BK / 16;                  // 4 / 4 / 8
    constexpr int ASZ  = BM * ROWB;                // 16K / 8K / 32K
    constexpr int BSZ  = (NPROD == 2) ? 2 * 128 * ROWB : 128 * ROWB;
    constexpr int STG  = ASZ + BSZ;                // 32K / 40K / 96K
    constexpr int NSTG = (MODE == 0) ? 3 : (MODE == 1) ? 2 : 1;
    constexpr int NITER = STG / 16 / 256;          // 8 / 10 / 24
    constexpr int AIT  = ASZ / 4096;               // A loader iters: 4 / 2 / -
    constexpr int WAITN = (NSTG >= 2) ? 1 : 0;

    extern __shared__ char smem[];
    const uint32_t sbase = smem_u32(smem);
    float* sq_s = reinterpret_cast<float*>(smem + NSTG * STG);
    const int tid = threadIdx.x;
    const int lane = tid & 31;
    const int wid = tid >> 5;
    const int warp_m = wid & 1;
    const int warp_n = wid >> 1;

    // block coordinates (triangle unrank for MODE 2)
    int bi = blockIdx.y, bj = blockIdx.x;
    if (MODE == 2) {
        int p = blockIdx.x;
        bi = 0;
        while (p >= 8 - bi) { p -= 8 - bi; ++bi; }
        bj = bi + p;
    }
    const int mBase = (MODE == 2) ? bi * 128 : (int)blockIdx.y * BM;
    const int nBase = (MODE == 2) ? bj * 128 : (int)blockIdx.x * 128;
    const int zb = (MODE == 2) ? blockIdx.z : 0;
    const size_t zrow = (size_t)zb * 1024;
    const int NC = K / BK;

    if (MODE == 1 && tid < BM) sq_s[tid] = 0.0f;

    float acc[MI][4][4];
#pragma unroll
    for (int i = 0; i < MI; i++)
#pragma unroll
        for (int j = 0; j < 4; j++)
#pragma unroll
            for (int q = 0; q < 4; q++) acc[i][j][q] = 0.0f;

    auto load_chunk = [&](int c, int stg) {
        const int k0 = c * BK;
        const uint32_t sb = sbase + stg * STG;
#pragma unroll
        for (int it = 0; it < NITER; ++it) {
            if (MODE == 2) {
                // it0-7 = A-hi (2048 16B chunks); it8-15 = B-hi; it16-23 = B-lo
                const int seg = it >> 3;
                const __half* src = (seg == 0) ? Ahi : (seg == 1) ? Bhi : Blo;
                const uint32_t soff = (uint32_t)seg * 32768u;
                const int rb = (seg == 0) ? mBase : nBase;
                const int l = (tid + it * 256) & 2047;
                const int row = l >> 4, sub = l & 15;
                const size_t goff = (zrow + rb + row) * (size_t)K + k0 + sub * 8;
                const uint32_t phys = ((sub & 7) ^ (row & 7)) | (sub & 8);
                const uint32_t dst = sb + soff + row * 256 + (phys << 4);
                cp16(dst, src + goff);
            } else {
                const __half* src;
                uint32_t soff;
                int rb, l;
                if (it < AIT) {                    // A-hi
                    src = Ahi; soff = 0u; rb = mBase;
                    l = tid + it * 256;
                } else if (it < AIT + 4) {         // B-hi
                    src = Bhi; soff = (uint32_t)ASZ; rb = nBase;
                    l = tid + (it - AIT) * 256;
                } else {                           // B-lo (NPROD==2 only)
                    src = Blo; soff = (uint32_t)ASZ + 16384u; rb = nBase;
                    l = tid + (it - AIT - 4) * 256;
                }
                const int row = l >> 3, sub = l & 7;
                const size_t goff = (zrow + rb + row) * (size_t)K + k0 + sub * 8;
                const uint32_t dst = sb + soff + row * 128 + ((sub ^ (row & 7)) << 4);
                cp16(dst, src + goff);
            }
        }
    };

    load_chunk(0, 0); cp_commit();
#pragma unroll
    for (int s = 1; s < NSTG; ++s) {
        if (s < NC) load_chunk(s, s);
        cp_commit();
    }

    // ldmatrix per-lane components
    const int a_row_l = lane & 15;
    const int a_cs = lane >> 4;
    const int b_row_l = (lane & 7) + ((lane >> 4) << 3);
    const int b_cs = (lane >> 3) & 1;

    for (int c = 0; c < NC; ++c) {
        asm volatile("cp.async.wait_group %0;" :: "n"(WAITN) : "memory");
        __syncthreads();
        const uint32_t base = sbase + (c % NSTG) * STG;
#pragma unroll
        for (int ks = 0; ks < KS; ++ks) {
            uint32_t Ah[MI][4];
#pragma unroll
            for (int mi = 0; mi < MI; ++mi) {
                const int row = warp_m * (BM / 2) + mi * 16 + a_row_l;
                uint32_t off;
                if (MODE == 2) {
                    const int ch = ks * 2 + a_cs;
                    off = (((ch & 7) ^ (a_row_l & 7)) | (ch & 8)) << 4;
                } else {
                    off = ((ks * 2 + a_cs) ^ (a_row_l & 7)) << 4;
                }
                ldsm4(Ah[mi], base + row * ROWB + off);
            }
            if (NSTG > 1 && ks == 0) {
                if (c + NSTG - 1 < NC) load_chunk(c + NSTG - 1, (c + NSTG - 1) % NSTG);
                cp_commit();
            }
#pragma unroll
            for (int np = 0; np < 2; ++np) {
                uint32_t Bh[4], Bl[4];
                const int n = warp_n * 32 + np * 16 + b_row_l;
                uint32_t off;
                if (MODE == 2) {
                    const int ch = ks * 2 + b_cs;
                    off = (((ch & 7) ^ (b_row_l & 7)) | (ch & 8)) << 4;
                } else {
                    off = ((ks * 2 + b_cs) ^ (b_row_l & 7)) << 4;
                }
                const uint32_t baddr = base + ASZ + n * ROWB + off;
                ldsm4(Bh, baddr);
                if (NPROD == 2) ldsm4(Bl, baddr + BSZ / 2);
#pragma unroll
                for (int half = 0; half < 2; ++half) {
                    const uint32_t bh[2] = {Bh[half * 2], Bh[half * 2 + 1]};
#pragma unroll
                    for (int mi = 0; mi < MI; ++mi)
                        mma_f16(acc[mi][np * 2 + half], Ah[mi], bh);
                    if (NPROD == 2) {
                        const uint32_t bl[2] = {Bl[half * 2], Bl[half * 2 + 1]};
#pragma unroll
                        for (int mi = 0; mi < MI; ++mi)
                            mma_f16(acc[mi][np * 2 + half], Ah[mi], bl);
                    }
                }
            }
        }
    }

    // ---------------- epilogue ----------------
    if (MODE == 2) {
        const float* sqg = bias + zb * 1024;
        float* Ob = Cf + (size_t)zb * 1024 * 1024;
        const bool diag = (bi == bj);
        float* T = reinterpret_cast<float*>(smem);   // reuse stage: 128x132 fp32
        __syncthreads();                             // stage fully consumed
#pragma unroll
        for (int mi = 0; mi < MI; ++mi) {
            const int lr0 = warp_m * 64 + mi * 16 + (lane >> 2);
            const int r0 = mBase + lr0;
            const float sr0 = sqg[r0], sr1 = sqg[r0 + 8];
#pragma unroll
            for (int ni = 0; ni < 4; ++ni) {
                const int lcol = warp_n * 32 + ni * 8 + 2 * (lane & 3);
                const int col = nBase + lcol;
                const float sc0 = sqg[col], sc1 = sqg[col + 1];
                const float* cc = acc[mi][ni];
                const float v00 = fmaxf(sr0 + sc0 - 2.0f * cc[0], 0.f);
                const float v01 = fmaxf(sr0 + sc1 - 2.0f * cc[1], 0.f);
                const float v10 = fmaxf(sr1 + sc0 - 2.0f * cc[2], 0.f);
                const float v11 = fmaxf(sr1 + sc1 - 2.0f * cc[3], 0.f);
                *reinterpret_cast<float2*>(Ob + (size_t)r0 * Ncols + col) =
                    make_float2(v00, v01);
                *reinterpret_cast<float2*>(Ob + (size_t)(r0 + 8) * Ncols + col) =
                    make_float2(v10, v11);
                if (!diag) {
                    T[lcol * 132 + lr0] = v00;
                    T[(lcol + 1) * 132 + lr0] = v01;
                    T[lcol * 132 + lr0 + 8] = v10;
                    T[(lcol + 1) * 132 + lr0 + 8] = v11;
                }
            }
        }
        if (!diag) {
            __syncthreads();
#pragma unroll
            for (int it = 0; it < 4; ++it) {
                const int j = (tid >> 3) + it * 32;
                const int c0 = (tid & 7) * 4;
                float* dst = Ob + (size_t)(nBase + j) * Ncols + mBase;
#pragma unroll
                for (int cq = 0; cq < 4; ++cq) {
                    const int c = c0 + cq * 32;
                    *reinterpret_cast<float4*>(dst + c) =
                        *reinterpret_cast<const float4*>(&T[j * 132 + c]);
                }
            }
        }
    } else {
#pragma unroll
        for (int mi = 0; mi < MI; ++mi) {
            const int r0 = mBase + warp_m * (BM / 2) + mi * 16 + (lane >> 2);
            float ss0 = 0.0f, ss1 = 0.0f;
#pragma unroll
            for (int ni = 0; ni < 4; ++ni) {
                const int col = nBase + warp_n * 32 + ni * 8 + 2 * (lane & 3);
                const float bz0 = __ldg(&bias[col]), bz1 = __ldg(&bias[col + 1]);
                const float* cc = acc[mi][ni];
                const float v00 = fmaxf(cc[0] + bz0, 0.f), v01 = fmaxf(cc[1] + bz1, 0.f);
                const float v10 = fmaxf(cc[2] + bz0, 0.f), v11 = fmaxf(cc[3] + bz1, 0.f);
                if (MODE == 1) { ss0 += v00 * v00 + v01 * v01; ss1 += v10 * v10 + v11 * v11; }
                const __half h00 = __float2half_rn(v00), h01 = __float2half_rn(v01);
                const __half h10 = __float2half_rn(v10), h11 = __float2half_rn(v11);
                __half2 hp0 = __halves2half2(h00, h01);
                __half2 hp1 = __halves2half2(h10, h11);
                *reinterpret_cast<uint32_t*>(Chi + (size_t)r0 * Ncols + col) =
                    *reinterpret_cast<uint32_t*>(&hp0);
                *reinterpret_cast<uint32_t*>(Chi + (size_t)(r0 + 8) * Ncols + col) =
                    *reinterpret_cast<uint32_t*>(&hp1);
                if (MODE == 1) {
                    const __half l00 = __float2half_rn(v00 - __half2float(h00));
                    const __half l01 = __float2half_rn(v01 - __half2float(h01));
                    const __half l10 = __float2half_rn(v10 - __half2float(h10));
                    const __half l11 = __float2half_rn(v11 - __half2float(h11));
                    __half2 lp0 = __halves2half2(l00, l01);
                    __half2 lp1 = __halves2half2(l10, l11);
                    *reinterpret_cast<uint32_t*>(Clo + (size_t)r0 * Ncols + col) =
                        *reinterpret_cast<uint32_t*>(&lp0);
                    *reinterpret_cast<uint32_t*>(Clo + (size_t)(r0 + 8) * Ncols + col) =
                        *reinterpret_cast<uint32_t*>(&lp1);
                }
            }
            if (MODE == 1) {
                atomicAdd(&sq_s[r0 - mBase], ss0);
                atomicAdd(&sq_s[r0 + 8 - mBase], ss1);
            }
        }
        if (MODE == 1) {
            __syncthreads();
            if (tid < BM) Cf[mBase + tid] = sq_s[tid];
        }
    }
}

static const int SMEM_M0 = 3 * 32768 + 512;   // 98816
static const int SMEM_M1 = 2 * 40960 + 512;   // 82432
static const int SMEM_M2 = 1 * 98304 + 512;   // 98816

// ---------------- fused conversion kernel ----------------
__global__ void prep_kernel(const float* __restrict__ batch,
                            const float* __restrict__ W1,
                            const float* __restrict__ W2,
                            __half* __restrict__ a_hi,
                            __half* __restrict__ w1t_hi,
                            __half* __restrict__ w2t_hi, __half* __restrict__ w2t_lo) {
    __shared__ float tile[32][33];
    const int b = blockIdx.x;
    const int tid = threadIdx.x;
    if (b < 16384) {
        const int i = b * 256 + tid;
        float4 v = reinterpret_cast<const float4*>(batch)[i];
        __half2 h0 = __halves2half2(__float2half_rn(v.x), __float2half_rn(v.y));
        __half2 h1 = __halves2half2(__float2half_rn(v.z), __float2half_rn(v.w));
        reinterpret_cast<uint2*>(a_hi)[i] =
            make_uint2(*reinterpret_cast<uint32_t*>(&h0), *reinterpret_cast<uint32_t*>(&h1));
        return;
    }
    const bool isW1 = (b < 16384 + 1024);
    const int idx = isW1 ? (b - 16384) : (b - 16384 - 1024);
    const int ncols = isW1 ? 1024 : 128;
    const int ntiles = ncols / 32;
    const int nb = (idx % ntiles) * 32;
    const int kb = (idx / ntiles) * 32;
    const float* W = isW1 ? W1 : W2;
    const int K = 1024;
    const int tx = tid & 31, ty = tid >> 5;   // (32, 8)
#pragma unroll
    for (int i = 0; i < 4; ++i)
        tile[ty + i * 8][tx] = W[(size_t)(kb + ty + i * 8) * ncols + nb + tx];
    __syncthreads();
#pragma unroll
    for (int i = 0; i < 4; ++i) {
        const int n = nb + ty + i * 8;
        const int k = kb + tx;
        const float v = tile[tx][ty + i * 8];
        const __half h = __float2half_rn(v);
        if (isW1) {
            w1t_hi[(size_t)n * K + k] = h;
        } else {
            w2t_hi[(size_t)n * K + k] = h;
            w2t_lo[(size_t)n * K + k] = __float2half_rn(v - __half2float(h));
        }
    }
}

// ---------------------------------------------------------------------------
extern "C" void kernel_launch(void* const* d_in, const int* in_sizes, int n_in,
                              void* d_out, int out_size) {
    const float* batch = (const float*)d_in[0];
    const float* W1    = (const float*)d_in[1];
    const float* b1    = (const float*)d_in[2];
    const float* W2    = (const float*)d_in[3];
    const float* b2    = (const float*)d_in[4];
    float* out = (float*)d_out;

    __half *a_hi, *h_hi, *w1t_hi, *w2t_hi, *w2t_lo, *t_hi, *t_lo;
    float *sq_ptr;
    cudaGetSymbolAddress((void**)&a_hi,   g_a_hi);
    cudaGetSymbolAddress((void**)&h_hi,   g_h_hi);
    cudaGetSymbolAddress((void**)&w1t_hi, g_w1t_hi);
    cudaGetSymbolAddress((void**)&w2t_hi, g_w2t_hi);
    cudaGetSymbolAddress((void**)&w2t_lo, g_w2t_lo);
    cudaGetSymbolAddress((void**)&t_hi,   g_t_hi);
    cudaGetSymbolAddress((void**)&t_lo,   g_t_lo);
    cudaGetSymbolAddress((void**)&sq_ptr, g_sq);

    cudaFuncSetAttribute(mma_gemm<0>, cudaFuncAttributeMaxDynamicSharedMemorySize, SMEM_M0);
    cudaFuncSetAttribute(mma_gemm<1>, cudaFuncAttributeMaxDynamicSharedMemorySize, SMEM_M1);
    cudaFuncSetAttribute(mma_gemm<2>, cudaFuncAttributeMaxDynamicSharedMemorySize, SMEM_M2);

    // 0) fused precision prep
    prep_kernel<<<16384 + 1024 + 128, 256>>>(batch, W1, W2, a_hi,
                                             w1t_hi, w2t_hi, w2t_lo);
    // 1) h = relu(batch @ W1 + b1) -> half hi   (BM=128, BK=64, 3-stage)
    {
        dim3 grid(H_DIM / 128, M_TOT / 128);   // (8, 128)
        mma_gemm<0><<<grid, 256, SMEM_M0>>>(
            a_hi, w1t_hi, nullptr, b1, nullptr, h_hi, nullptr, D_DIM, H_DIM);
    }
    // 2) t = relu(h @ W2 + b2) -> half hi/lo + row sumsq   (BK=64, 2-stage)
    {
        dim3 grid(R_DIM / 128, M_TOT / 64);    // (1, 256)
        mma_gemm<1><<<grid, 256, SMEM_M1>>>(
            h_hi, w2t_hi, w2t_lo, b2, sq_ptr, t_hi, t_lo, H_DIM, R_DIM);
    }
    // 3) symmetric pairwise distances   (BK=128, single stage)
    {
        dim3 grid(36, 1, B_DIM);
        mma_gemm<2><<<grid, 256, SMEM_M2>>>(
            t_hi, t_hi, t_lo, sq_ptr, out, nullptr, nullptr, R_DIM, L_DIM);
    }
}

// round 16
// speedup vs baseline: 1.0654x; 1.0654x over previous
#include <cuda_runtime.h>
#include <cuda_fp16.h>
#include <cstdint>
#include <cstddef>

// Shapes: batch[16,1024,1024] -> M=16384,K=1024 ; W1[1024,1024] ; W2[1024,128]
// out[16,1024,1024] fp32.
static const int M_TOT = 16384;
static const int D_DIM = 1024;
static const int H_DIM = 1024;
static const int R_DIM = 128;
static const int L_DIM = 1024;
static const int B_DIM = 16;

// ---- scratch (__device__ globals; no runtime allocation allowed) ----
__device__ __align__(256) __half g_a_hi[(size_t)16384 * 1024];
__device__ __align__(256) __half g_h_hi[(size_t)16384 * 1024];
__device__ __align__(256) __half g_w1t_hi[(size_t)1024 * 1024];
__device__ __align__(256) __half g_w2t_hi[(size_t)128 * 1024];
__device__ __align__(256) __half g_w2t_lo[(size_t)128 * 1024];
__device__ __align__(256) __half g_t_hi[(size_t)16384 * 128];
__device__ __align__(256) __half g_t_lo[(size_t)16384 * 128];
__device__ __align__(256) float g_sq[16384];

// ---------------- PTX helpers ----------------
__device__ __forceinline__ uint32_t smem_u32(const void* p) {
    uint32_t a;
    asm("{ .reg .u64 t; cvta.to.shared.u64 t, %1; cvt.u32.u64 %0, t; }" : "=r"(a) : "l"(p));
    return a;
}
__device__ __forceinline__ void cp16(uint32_t saddr, const void* g) {
    asm volatile("cp.async.cg.shared.global [%0], [%1], 16;" :: "r"(saddr), "l"(g));
}
__device__ __forceinline__ void cp_commit() {
    asm volatile("cp.async.commit_group;" ::: "memory");
}
__device__ __forceinline__ void ldsm4(uint32_t* r, uint32_t addr) {
    asm volatile("ldmatrix.sync.aligned.m8n8.x4.shared.b16 {%0,%1,%2,%3}, [%4];"
                 : "=r"(r[0]), "=r"(r[1]), "=r"(r[2]), "=r"(r[3]) : "r"(addr));
}
__device__ __forceinline__ void mma_f16(float* c, const uint32_t* a, const uint32_t* b) {
    asm volatile(
        "mma.sync.aligned.m16n8k16.row.col.f32.f16.f16.f32 "
        "{%0,%1,%2,%3}, {%4,%5,%6,%7}, {%8,%9}, {%0,%1,%2,%3};"
        : "+f"(c[0]), "+f"(c[1]), "+f"(c[2]), "+f"(c[3])
        : "r"(a[0]), "r"(a[1]), "r"(a[2]), "r"(a[3]), "r"(b[0]), "r"(b[1]));
}

// ---------------- unified tensor-core GEMM ------------------------
// acc = A @ B^T, fp16 operands, fp32 accumulate.
// MODE 0 (GEMM1): 128 thr (4 warps 2x2, tile 64x64), BK=64, 3 stages, 1 product
// MODE 1 (GEMM2): 256 thr (8 warps 2x4, tile 32x32), BM=64, BK=64, 2 stg, 2 prod
// MODE 2 (DIST):  256 thr (8 warps 2x4, tile 64x32), BK=128 single stage, 2 prod;
//                 SYMMETRIC 36 triangle pairs; direct + mirrored block.
template <int MODE>
__global__ __launch_bounds__((MODE == 0) ? 128 : 256, 2)
void mma_gemm(const __half* __restrict__ Ahi,
              const __half* __restrict__ Bhi, const __half* __restrict__ Blo,
              const float* __restrict__ bias,
              float* __restrict__ Cf,
              __half* __restrict__ Chi, __half* __restrict__ Clo,
              int K, int Ncols) {
    constexpr int NPROD = (MODE == 0) ? 1 : 2;
    constexpr int NT   = (MODE == 0) ? 128 : 256;
    constexpr int MI   = (MODE == 1) ? 2 : 4;      // 16-row frags per warp
    constexpr int NP   = (MODE == 0) ? 4 : 2;      // 16-col groups per warp
    constexpr int WN   = NP * 16;                  // warp n-extent
    constexpr int BM   = MI * 32;                  // 128 / 64 / 128
    constexpr int BK   = (MODE == 2) ? 128 : 64;
    constexpr int ROWB = BK * 2;
    constexpr int KS   = BK / 16;
    constexpr int ASZ  = BM * ROWB;                // 16K / 8K / 32K
    constexpr int BHSZ = 128 * ROWB;               // 16K / 16K / 32K
    constexpr int BSZ  = NPROD * BHSZ;
    constexpr int STG  = ASZ + BSZ;                // 32K / 40K / 96K
    constexpr int NSTG = (MODE == 0) ? 3 : (MODE == 1) ? 2 : 1;
    constexpr int RSH  = (BK == 128) ? 4 : 3;
    constexpr int SMSK = (BK == 128) ? 15 : 7;

    extern __shared__ char smem[];
    const uint32_t sbase = smem_u32(smem);
    float* sq_s = reinterpret_cast<float*>(smem + NSTG * STG);
    const int tid = threadIdx.x;
    const int lane = tid & 31;
    const int wid = tid >> 5;
    const int warp_m = wid & 1;
    const int warp_n = wid >> 1;                   // 0..1 (MODE0) / 0..3

    // block coordinates (triangle unrank for MODE 2)
    int bi = blockIdx.y, bj = blockIdx.x;
    if (MODE == 2) {
        int p = blockIdx.x;
        bi = 0;
        while (p >= 8 - bi) { p -= 8 - bi; ++bi; }
        bj = bi + p;
    }
    const int mBase = (MODE == 2) ? bi * 128 : (int)blockIdx.y * BM;
    const int nBase = (MODE == 2) ? bj * 128 : (int)blockIdx.x * 128;
    const int zb = (MODE == 2) ? blockIdx.z : 0;
    const size_t zrow = (size_t)zb * 1024;
    const int NC = K / BK;

    if (MODE == 1 && tid < BM) sq_s[tid] = 0.0f;

    float acc[MI][2 * NP][4];
#pragma unroll
    for (int i = 0; i < MI; i++)
#pragma unroll
        for (int j = 0; j < 2 * NP; j++)
#pragma unroll
            for (int q = 0; q < 4; q++) acc[i][j][q] = 0.0f;

    auto swz = [](int sub, int row) -> uint32_t {
        if (BK == 128) return (uint32_t)(((sub & 7) ^ (row & 7)) | (sub & 8));
        return (uint32_t)(sub ^ (row & 7));
    };

    auto load_chunk = [&](int c, int stg) {
        const int k0 = c * BK;
        const uint32_t sb = sbase + stg * STG;
#pragma unroll
        for (int i = 0; i < ASZ / 16 / NT; ++i) {      // A-hi
            const int l = tid + i * NT;
            const int row = l >> RSH, sub = l & SMSK;
            const size_t goff = (zrow + mBase + row) * (size_t)K + k0 + sub * 8;
            cp16(sb + row * ROWB + (swz(sub, row) << 4), Ahi + goff);
        }
#pragma unroll
        for (int i = 0; i < BHSZ / 16 / NT; ++i) {     // B-hi
            const int l = tid + i * NT;
            const int row = l >> RSH, sub = l & SMSK;
            const size_t goff = (zrow + nBase + row) * (size_t)K + k0 + sub * 8;
            cp16(sb + ASZ + row * ROWB + (swz(sub, row) << 4), Bhi + goff);
        }
        if (NPROD == 2) {
#pragma unroll
            for (int i = 0; i < BHSZ / 16 / NT; ++i) { // B-lo
                const int l = tid + i * NT;
                const int row = l >> RSH, sub = l & SMSK;
                const size_t goff = (zrow + nBase + row) * (size_t)K + k0 + sub * 8;
                cp16(sb + ASZ + BHSZ + row * ROWB + (swz(sub, row) << 4), Blo + goff);
            }
        }
    };

    load_chunk(0, 0); cp_commit();
#pragma unroll
    for (int s = 1; s < NSTG; ++s) {
        if (s < NC) load_chunk(s, s);
        cp_commit();
    }

    // ldsm per-lane components
    const int a_row_l = lane & 15;
    const int a_cs = lane >> 4;
    const int b_row_l = (lane & 7) + ((lane >> 4) << 3);
    const int b_cs = (lane >> 3) & 1;

    for (int c = 0; c < NC; ++c) {
        if (NSTG > 1) asm volatile("cp.async.wait_group 1;" ::: "memory");
        else          asm volatile("cp.async.wait_group 0;" ::: "memory");
        __syncthreads();
        const uint32_t base = sbase + (c % NSTG) * STG;
#pragma unroll
        for (int ks = 0; ks < KS; ++ks) {
            uint32_t Ah[MI][4];
#pragma unroll
            for (int mi = 0; mi < MI; ++mi) {
                const int row = warp_m * (BM / 2) + mi * 16 + a_row_l;
                const uint32_t off = swz(ks * 2 + a_cs, a_row_l) << 4;
                ldsm4(Ah[mi], base + row * ROWB + off);
            }
            if (NSTG > 1 && ks == 0) {
                if (c + NSTG - 1 < NC) load_chunk(c + NSTG - 1, (c + NSTG - 1) % NSTG);
                cp_commit();
            }
#pragma unroll
            for (int np = 0; np < NP; ++np) {
                uint32_t Bh[4], Bl[4];
                const int n = warp_n * WN + np * 16 + b_row_l;
                const uint32_t off = swz(ks * 2 + b_cs, b_row_l) << 4;
                const uint32_t baddr = base + ASZ + n * ROWB + off;
                ldsm4(Bh, baddr);
                if (NPROD == 2) ldsm4(Bl, baddr + BHSZ);
#pragma unroll
                for (int half = 0; half < 2; ++half) {
                    const uint32_t bh[2] = {Bh[half * 2], Bh[half * 2 + 1]};
#pragma unroll
                    for (int mi = 0; mi < MI; ++mi)
                        mma_f16(acc[mi][np * 2 + half], Ah[mi], bh);
                    if (NPROD == 2) {
                        const uint32_t bl[2] = {Bl[half * 2], Bl[half * 2 + 1]};
#pragma unroll
                        for (int mi = 0; mi < MI; ++mi)
                            mma_f16(acc[mi][np * 2 + half], Ah[mi], bl);
                    }
                }
            }
        }
    }

    // ---------------- epilogue ----------------
    if (MODE == 2) {
        const float* sqg = bias + zb * 1024;
        float* Ob = Cf + (size_t)zb * 1024 * 1024;
        const bool diag = (bi == bj);
        float* T = reinterpret_cast<float*>(smem);   // reuse stage: 128x132 fp32
        __syncthreads();                             // stage fully consumed
#pragma unroll
        for (int mi = 0; mi < MI; ++mi) {
            const int lr0 = warp_m * 64 + mi * 16 + (lane >> 2);
            const int r0 = mBase + lr0;
            const float sr0 = sqg[r0], sr1 = sqg[r0 + 8];
#pragma unroll
            for (int ni = 0; ni < 2 * NP; ++ni) {
                const int lcol = warp_n * WN + ni * 8 + 2 * (lane & 3);
                const int col = nBase + lcol;
                const float sc0 = sqg[col], sc1 = sqg[col + 1];
                const float* cc = acc[mi][ni];
                const float v00 = fmaxf(sr0 + sc0 - 2.0f * cc[0], 0.f);
                const float v01 = fmaxf(sr0 + sc1 - 2.0f * cc[1], 0.f);
                const float v10 = fmaxf(sr1 + sc0 - 2.0f * cc[2], 0.f);
                const float v11 = fmaxf(sr1 + sc1 - 2.0f * cc[3], 0.f);
                *reinterpret_cast<float2*>(Ob + (size_t)r0 * Ncols + col) =
                    make_float2(v00, v01);
                *reinterpret_cast<float2*>(Ob + (size_t)(r0 + 8) * Ncols + col) =
                    make_float2(v10, v11);
                if (!diag) {
                    T[lcol * 132 + lr0] = v00;
                    T[(lcol + 1) * 132 + lr0] = v01;
                    T[lcol * 132 + lr0 + 8] = v10;
                    T[(lcol + 1) * 132 + lr0 + 8] = v11;
                }
            }
        }
        if (!diag) {
            __syncthreads();
#pragma unroll
            for (int it = 0; it < 4; ++it) {
                const int j = (tid >> 3) + it * 32;
                const int c0 = (tid & 7) * 4;
                float* dst = Ob + (size_t)(nBase + j) * Ncols + mBase;
#pragma unroll
                for (int cq = 0; cq < 4; ++cq) {
                    const int c = c0 + cq * 32;
                    *reinterpret_cast<float4*>(dst + c) =
                        *reinterpret_cast<const float4*>(&T[j * 132 + c]);
                }
            }
        }
    } else {
#pragma unroll
        for (int mi = 0; mi < MI; ++mi) {
            const int r0 = mBase + warp_m * (BM / 2) + mi * 16 + (lane >> 2);
            float ss0 = 0.0f, ss1 = 0.0f;
#pragma unroll
            for (int ni = 0; ni < 2 * NP; ++ni) {
                const int col = nBase + warp_n * WN + ni * 8 + 2 * (lane & 3);
                const float bz0 = __ldg(&bias[col]), bz1 = __ldg(&bias[col + 1]);
                const float* cc = acc[mi][ni];
                const float v00 = fmaxf(cc[0] + bz0, 0.f), v01 = fmaxf(cc[1] + bz1, 0.f);
                const float v10 = fmaxf(cc[2] + bz0, 0.f), v11 = fmaxf(cc[3] + bz1, 0.f);
                if (MODE == 1) { ss0 += v00 * v00 + v01 * v01; ss1 += v10 * v10 + v11 * v11; }
                const __half h00 = __float2half_rn(v00), h01 = __float2half_rn(v01);
                const __half h10 = __float2half_rn(v10), h11 = __float2half_rn(v11);
                __half2 hp0 = __halves2half2(h00, h01);
                __half2 hp1 = __halves2half2(h10, h11);
                *reinterpret_cast<uint32_t*>(Chi + (size_t)r0 * Ncols + col) =
                    *reinterpret_cast<uint32_t*>(&hp0);
                *reinterpret_cast<uint32_t*>(Chi + (size_t)(r0 + 8) * Ncols + col) =
                    *reinterpret_cast<uint32_t*>(&hp1);
                if (MODE == 1) {
                    const __half l00 = __float2half_rn(v00 - __half2float(h00));
                    const __half l01 = __float2half_rn(v01 - __half2float(h01));
                    const __half l10 = __float2half_rn(v10 - __half2float(h10));
                    const __half l11 = __float2half_rn(v11 - __half2float(h11));
                    __half2 lp0 = __halves2half2(l00, l01);
                    __half2 lp1 = __halves2half2(l10, l11);
                    *reinterpret_cast<uint32_t*>(Clo + (size_t)r0 * Ncols + col) =
                        *reinterpret_cast<uint32_t*>(&lp0);
                    *reinterpret_cast<uint32_t*>(Clo + (size_t)(r0 + 8) * Ncols + col) =
                        *reinterpret_cast<uint32_t*>(&lp1);
                }
            }
            if (MODE == 1) {
                atomicAdd(&sq_s[r0 - mBase], ss0);
                atomicAdd(&sq_s[r0 + 8 - mBase], ss1);
            }
        }
        if (MODE == 1) {
            __syncthreads();
            if (tid < BM) Cf[mBase + tid] = sq_s[tid];
        }
    }
}

static const int SMEM_M0 = 3 * 32768 + 512;   // 98816
static const int SMEM_M1 = 2 * 40960 + 512;   // 82432
static const int SMEM_M2 = 1 * 98304 + 512;   // 98816

// ---------------- fused conversion kernel ----------------
__global__ void prep_kernel(const float* __restrict__ batch,
                            const float* __restrict__ W1,
                            const float* __restrict__ W2,
                            __half* __restrict__ a_hi,
                            __half* __restrict__ w1t_hi,
                            __half* __restrict__ w2t_hi, __half* __restrict__ w2t_lo) {
    __shared__ float tile[32][33];
    const int b = blockIdx.x;
    const int tid = threadIdx.x;
    if (b < 16384) {
        const int i = b * 256 + tid;
        float4 v = reinterpret_cast<const float4*>(batch)[i];
        __half2 h0 = __halves2half2(__float2half_rn(v.x), __float2half_rn(v.y));
        __half2 h1 = __halves2half2(__float2half_rn(v.z), __float2half_rn(v.w));
        reinterpret_cast<uint2*>(a_hi)[i] =
            make_uint2(*reinterpret_cast<uint32_t*>(&h0), *reinterpret_cast<uint32_t*>(&h1));
        return;
    }
    const bool isW1 = (b < 16384 + 1024);
    const int idx = isW1 ? (b - 16384) : (b - 16384 - 1024);
    const int ncols = isW1 ? 1024 : 128;
    const int ntiles = ncols / 32;
    const int nb = (idx % ntiles) * 32;
    const int kb = (idx / ntiles) * 32;
    const float* W = isW1 ? W1 : W2;
    const int K = 1024;
    const int tx = tid & 31, ty = tid >> 5;   // (32, 8)
#pragma unroll
    for (int i = 0; i < 4; ++i)
        tile[ty + i * 8][tx] = W[(size_t)(kb + ty + i * 8) * ncols + nb + tx];
    __syncthreads();
#pragma unroll
    for (int i = 0; i < 4; ++i) {
        const int n = nb + ty + i * 8;
        const int k = kb + tx;
        const float v = tile[tx][ty + i * 8];
        const __half h = __float2half_rn(v);
        if (isW1) {
            w1t_hi[(size_t)n * K + k] = h;
        } else {
            w2t_hi[(size_t)n * K + k] = h;
            w2t_lo[(size_t)n * K + k] = __float2half_rn(v - __half2float(h));
        }
    }
}

// ---------------------------------------------------------------------------
extern "C" void kernel_launch(void* const* d_in, const int* in_sizes, int n_in,
                              void* d_out, int out_size) {
    const float* batch = (const float*)d_in[0];
    const float* W1    = (const float*)d_in[1];
    const float* b1    = (const float*)d_in[2];
    const float* W2    = (const float*)d_in[3];
    const float* b2    = (const float*)d_in[4];
    float* out = (float*)d_out;

    __half *a_hi, *h_hi, *w1t_hi, *w2t_hi, *w2t_lo, *t_hi, *t_lo;
    float *sq_ptr;
    cudaGetSymbolAddress((void**)&a_hi,   g_a_hi);
    cudaGetSymbolAddress((void**)&h_hi,   g_h_hi);
    cudaGetSymbolAddress((void**)&w1t_hi, g_w1t_hi);
    cudaGetSymbolAddress((void**)&w2t_hi, g_w2t_hi);
    cudaGetSymbolAddress((void**)&w2t_lo, g_w2t_lo);
    cudaGetSymbolAddress((void**)&t_hi,   g_t_hi);
    cudaGetSymbolAddress((void**)&t_lo,   g_t_lo);
    cudaGetSymbolAddress((void**)&sq_ptr, g_sq);

    cudaFuncSetAttribute(mma_gemm<0>, cudaFuncAttributeMaxDynamicSharedMemorySize, SMEM_M0);
    cudaFuncSetAttribute(mma_gemm<1>, cudaFuncAttributeMaxDynamicSharedMemorySize, SMEM_M1);
    cudaFuncSetAttribute(mma_gemm<2>, cudaFuncAttributeMaxDynamicSharedMemorySize, SMEM_M2);

    // 0) fused precision prep
    prep_kernel<<<16384 + 1024 + 128, 256>>>(batch, W1, W2, a_hi,
                                             w1t_hi, w2t_hi, w2t_lo);
    // 1) h = relu(batch @ W1 + b1) -> half hi   (128 threads, 4 warps 2x2)
    {
        dim3 grid(H_DIM / 128, M_TOT / 128);   // (8, 128)
        mma_gemm<0><<<grid, 128, SMEM_M0>>>(
            a_hi, w1t_hi, nullptr, b1, nullptr, h_hi, nullptr, D_DIM, H_DIM);
    }
    // 2) t = relu(h @ W2 + b2) -> half hi/lo + row sumsq   (BK=64, 2-stage)
    {
        dim3 grid(R_DIM / 128, M_TOT / 64);    // (1, 256)
        mma_gemm<1><<<grid, 256, SMEM_M1>>>(
            h_hi, w2t_hi, w2t_lo, b2, sq_ptr, t_hi, t_lo, H_DIM, R_DIM);
    }
    // 3) symmetric pairwise distances   (BK=128, single stage)
    {
        dim3 grid(36, 1, B_DIM);
        mma_gemm<2><<<grid, 256, SMEM_M2>>>(
            t_hi, t_hi, t_lo, sq_ptr, out, nullptr, nullptr, R_DIM, L_DIM);
    }
}